// round 13
// baseline (speedup 1.0000x reference)
#include <cuda_runtime.h>
#include <cuda_fp16.h>
#include <cstdint>

#define NROWS 8192
#define DDIM  256

// ---------------- device scratch (allocation-free) ----------------
// fp16 copies; within each 32-column K-group, 16B granule q (8 fp16) holds
// orig cols {2q,2q+1, 2q+8,2q+9, 2q+16,2q+17, 2q+24,2q+25} — exactly thread
// tig=q's m16n8k16 fragments for BOTH k16-steps of the group. One LDS.128
// per row per 32-col chunk feeds 2 MMAs' worth of fragments.
__device__ __half g_h[2][NROWS * DDIM];
__device__ float  g_sq[2][NROWS];        // exact fp32 row norms

// ---------------- helpers ----------------
__device__ __forceinline__ uint32_t smem_u32(const void* p) {
    uint32_t a;
    asm("{ .reg .u64 t; cvta.to.shared.u64 t, %1; cvt.u32.u64 %0, t; }" : "=r"(a) : "l"(p));
    return a;
}
__device__ __forceinline__ uint4 lds128(uint32_t a) {
    uint4 v;
    asm volatile("ld.shared.v4.b32 {%0,%1,%2,%3}, [%4];"
                 : "=r"(v.x), "=r"(v.y), "=r"(v.z), "=r"(v.w) : "r"(a));
    return v;
}
__device__ __forceinline__ void cp16(uint32_t dst, const void* src) {
    asm volatile("cp.async.cg.shared.global [%0], [%1], 16;" :: "r"(dst), "l"(src));
}
__device__ __forceinline__ void cp_commit() {
    asm volatile("cp.async.commit_group;" ::: "memory");
}
template <int N> __device__ __forceinline__ void cp_wait() {
    asm volatile("cp.async.wait_group %0;" :: "n"(N) : "memory");
}
__device__ __forceinline__ void mma_f16(float* c, uint32_t a0, uint32_t a1,
                                        uint32_t a2, uint32_t a3,
                                        uint32_t b0, uint32_t b1) {
    asm volatile(
        "mma.sync.aligned.m16n8k16.row.col.f32.f16.f16.f32 "
        "{%0,%1,%2,%3}, {%4,%5,%6,%7}, {%8,%9}, {%0,%1,%2,%3};"
        : "+f"(c[0]), "+f"(c[1]), "+f"(c[2]), "+f"(c[3])
        : "r"(a0), "r"(a1), "r"(a2), "r"(a3), "r"(b0), "r"(b1));
}

// ---------------- prep: fp16 convert + 32-wide K-permute + exact row norms ----------------
__global__ void prep_kernel(const float* __restrict__ x1, const float* __restrict__ x2) {
    __shared__ float buf[8][256];
    int wib   = threadIdx.x >> 5;
    int gw    = (blockIdx.x * blockDim.x + threadIdx.x) >> 5;  // global warp [0,16384)
    int lane  = threadIdx.x & 31;
    int which = gw >> 13;                 // 0 -> x1, 1 -> x2
    int row   = gw & (NROWS - 1);
    const float4* src = reinterpret_cast<const float4*>((which ? x2 : x1) + (size_t)row * DDIM);

    float s = 0.f;
#pragma unroll
    for (int i = 0; i < 2; i++) {
        int q = lane + 32 * i;            // 64 float4 per row
        float4 v = src[q];
        s += v.x * v.x + v.y * v.y + v.z * v.z + v.w * v.w;   // exact fp32 norm
        *reinterpret_cast<float4*>(&buf[wib][q * 4]) = v;
    }
    __syncwarp();
#pragma unroll
    for (int off = 16; off; off >>= 1) s += __shfl_xor_sync(0xffffffff, s, off);
    if (lane == 0) g_sq[which][row] = s;

    // permuted fp16 writeback, one uint32 (2 halves) per thread-iter:
    // dst pair (j0, j0+1) <- cols (grp + 2q + 8m, +1), q=(j0&31)>>3, m=((j0&7)>>1)
    uint32_t* dst32 = reinterpret_cast<uint32_t*>(&g_h[which][(size_t)row * DDIM]);
#pragma unroll
    for (int i = 0; i < 4; i++) {
        int pidx = i * 32 + lane;         // pair index 0..127
        int j0   = pidx * 2;
        int grp  = j0 & ~31;
        int p    = j0 & 31;
        int q    = p >> 3;
        int m    = (p & 7) >> 1;
        int col  = grp + 2 * q + 8 * m;
        __half h0 = __float2half_rn(buf[wib][col]);
        __half h1 = __float2half_rn(buf[wib][col + 1]);
        dst32[pidx] = (uint32_t)__half_as_ushort(h0)
                    | ((uint32_t)__half_as_ushort(h1) << 16);
    }
}

// ---------------- main GEMM + epilogue ----------------
#define BM 128
#define BN 128
#define BK 32
#define NK (DDIM / BK)            // 8 K-iterations
#define STAGES 4
#define ROWB 64                   // 32 fp16 per smem row; no swizzle needed
#define MAT_BYTES (BM * ROWB)     // 8192
#define STAGE_BYTES (2 * MAT_BYTES)         // 16384
#define SMEM_TOTAL (STAGES * STAGE_BYTES)   // 65536 -> 2 CTAs/SM

__global__ void __launch_bounds__(256, 2)
cdist_kernel(float* __restrict__ out) {
    extern __shared__ char smem_raw[];
    const uint32_t sbase = smem_u32(smem_raw);

    const int tid = threadIdx.x;
    const int wid = tid >> 5;
    const int lid = tid & 31;
    const int m0 = blockIdx.y * BM;
    const int n0 = blockIdx.x * BN;
    const int g   = lid >> 2;         // 0..7
    const int tig = lid & 3;          // 0..3
    const int wm = (wid & 1) * 64;    // warp m-offset (2 warps in M)
    const int wn = (wid >> 1) * 32;   // warp n-offset (4 warps in N)

    // ---- loop-invariant cp.async addressing ----
    // 512 granules (16B) per matrix per stage: 128 rows x 4; 2 per thread.
    const int crow = tid >> 2;        // 0..63, second batch at +64
    const int kq   = tid & 3;         // granule within 32-col chunk
    const char* gA = (const char*)g_h[0]
                   + ((size_t)(m0 + crow) * DDIM + (size_t)kq * 8) * 2;
    const char* gB = (const char*)g_h[1]
                   + ((size_t)(n0 + crow) * DDIM + (size_t)kq * 8) * 2;
    const uint32_t sdA = sbase + (uint32_t)crow * ROWB + (uint32_t)kq * 16u;
    const uint32_t sdB = sdA + MAT_BYTES;

    auto load_stage = [&](int kc, int s) {   // kc, s compile-time under unroll
#pragma unroll
        for (int i = 0; i < 2; i++) {
            cp16(sdA + s * STAGE_BYTES + i * (64 * ROWB), gA + kc * 64 + i * (64 * DDIM * 2));
            cp16(sdB + s * STAGE_BYTES + i * (64 * ROWB), gB + kc * 64 + i * (64 * DDIM * 2));
        }
        cp_commit();
    };

    // ---- loop-invariant fragment bases (all mt/nt offsets are immediates) ----
    const uint32_t abase = sbase + (uint32_t)(wm + g) * ROWB + (uint32_t)tig * 16u;
    const uint32_t bbase = sbase + MAT_BYTES + (uint32_t)(wn + g) * ROWB + (uint32_t)tig * 16u;

    // prologue: STAGES-1 stages in flight
    load_stage(0, 0);
    load_stage(1, 1);
    load_stage(2, 2);

    float c[4][4][4];
#pragma unroll
    for (int mt = 0; mt < 4; mt++)
#pragma unroll
        for (int nt = 0; nt < 4; nt++)
#pragma unroll
            for (int i = 0; i < 4; i++) c[mt][nt][i] = 0.f;

#pragma unroll
    for (int kc = 0; kc < NK; kc++) {
        cp_wait<STAGES - 2>();     // stage kc landed
        __syncthreads();           // all warps done reading buf being refilled

        if (kc + STAGES - 1 < NK) load_stage(kc + STAGES - 1, (kc + STAGES - 1) % STAGES);
        else cp_commit();          // empty group keeps wait_group arithmetic uniform

        const uint32_t soff = (uint32_t)((kc % STAGES) * STAGE_BYTES);
        const uint32_t ab = abase + soff;
        const uint32_t bb = bbase + soff;

        // fragment loads: one LDS.128 per row covers BOTH k16-steps
        uint4 alo[4], ahi[4], bv[4];
#pragma unroll
        for (int nt = 0; nt < 4; nt++)
            bv[nt] = lds128(bb + nt * (8 * ROWB));          // rows wn+nt*8+g
#pragma unroll
        for (int mt = 0; mt < 4; mt++) {
            alo[mt] = lds128(ab + mt * (16 * ROWB));        // row g
            ahi[mt] = lds128(ab + mt * (16 * ROWB) + 8 * ROWB);  // row g+8
        }

        // k16-step 0: frags .x/.y ; dep distance 16 to step 1
#pragma unroll
        for (int mt = 0; mt < 4; mt++)
#pragma unroll
            for (int nt = 0; nt < 4; nt++)
                mma_f16(c[mt][nt], alo[mt].x, ahi[mt].x, alo[mt].y, ahi[mt].y,
                        bv[nt].x, bv[nt].y);
        // k16-step 1: frags .z/.w
#pragma unroll
        for (int mt = 0; mt < 4; mt++)
#pragma unroll
            for (int nt = 0; nt < 4; nt++)
                mma_f16(c[mt][nt], alo[mt].z, ahi[mt].z, alo[mt].w, ahi[mt].w,
                        bv[nt].z, bv[nt].w);
    }

    // ---- epilogue: d = sqrt(max(sq1 + sq2 - 2*cross, 0)) ----
    const float* sq1 = g_sq[0] + m0;
    const float* sq2 = g_sq[1] + n0;
#pragma unroll
    for (int mt = 0; mt < 4; mt++) {
        int r0 = wm + mt * 16 + g;
        float s1a = sq1[r0];
        float s1b = sq1[r0 + 8];
        float* o0 = out + (size_t)(m0 + r0) * NROWS + n0;
        float* o1 = o0 + (size_t)8 * NROWS;
#pragma unroll
        for (int nt = 0; nt < 4; nt++) {
            int cc = wn + nt * 8 + 2 * tig;
            float s2a = sq2[cc];
            float s2b = sq2[cc + 1];
            float2 v0, v1;
            v0.x = sqrtf(fmaxf(fmaf(-2.f, c[mt][nt][0], s1a + s2a), 0.f));
            v0.y = sqrtf(fmaxf(fmaf(-2.f, c[mt][nt][1], s1a + s2b), 0.f));
            v1.x = sqrtf(fmaxf(fmaf(-2.f, c[mt][nt][2], s1b + s2a), 0.f));
            v1.y = sqrtf(fmaxf(fmaf(-2.f, c[mt][nt][3], s1b + s2b), 0.f));
            *reinterpret_cast<float2*>(o0 + cc) = v0;
            *reinterpret_cast<float2*>(o1 + cc) = v1;
        }
    }
}

// ---------------- launch ----------------
extern "C" void kernel_launch(void* const* d_in, const int* in_sizes, int n_in,
                              void* d_out, int out_size) {
    (void)in_sizes; (void)n_in; (void)out_size;
    const float* x1 = (const float*)d_in[0];
    const float* x2 = (const float*)d_in[1];
    float* out = (float*)d_out;

    prep_kernel<<<2048, 256>>>(x1, x2);

    static bool attr_set = false;
    if (!attr_set) {
        cudaFuncSetAttribute(cdist_kernel,
                             cudaFuncAttributeMaxDynamicSharedMemorySize, SMEM_TOTAL);
        attr_set = true;
    }
    dim3 grid(NROWS / BN, NROWS / BM);   // (64, 64)
    cdist_kernel<<<grid, 256, SMEM_TOTAL>>>(out);
}

// round 14
// speedup vs baseline: 1.2990x; 1.2990x over previous
#include <cuda_runtime.h>
#include <cuda_fp16.h>
#include <cstdint>

#define NROWS 8192
#define DDIM  256

// ---------------- device scratch (allocation-free) ----------------
// fp16 copies; within each 32-column K-group, 16B granule q (8 fp16) holds
// orig cols {2q,2q+1, 2q+8,2q+9, 2q+16,2q+17, 2q+24,2q+25} — thread tig=q's
// m16n8k16 fragments for BOTH k16-steps. One LDS.128 per row per 32-col chunk.
__device__ __half g_h[2][NROWS * DDIM];
__device__ float  g_sq[2][NROWS];        // exact fp32 row norms

// ---------------- helpers ----------------
__device__ __forceinline__ uint32_t smem_u32(const void* p) {
    uint32_t a;
    asm("{ .reg .u64 t; cvta.to.shared.u64 t, %1; cvt.u32.u64 %0, t; }" : "=r"(a) : "l"(p));
    return a;
}
__device__ __forceinline__ uint4 lds128(uint32_t a) {
    uint4 v;
    asm volatile("ld.shared.v4.b32 {%0,%1,%2,%3}, [%4];"
                 : "=r"(v.x), "=r"(v.y), "=r"(v.z), "=r"(v.w) : "r"(a));
    return v;
}
__device__ __forceinline__ void cp16(uint32_t dst, const void* src) {
    asm volatile("cp.async.cg.shared.global [%0], [%1], 16;" :: "r"(dst), "l"(src));
}
__device__ __forceinline__ void cp_commit() {
    asm volatile("cp.async.commit_group;" ::: "memory");
}
template <int N> __device__ __forceinline__ void cp_wait() {
    asm volatile("cp.async.wait_group %0;" :: "n"(N) : "memory");
}
__device__ __forceinline__ void mma_f16(float* c, uint32_t a0, uint32_t a1,
                                        uint32_t a2, uint32_t a3,
                                        uint32_t b0, uint32_t b1) {
    asm volatile(
        "mma.sync.aligned.m16n8k16.row.col.f32.f16.f16.f32 "
        "{%0,%1,%2,%3}, {%4,%5,%6,%7}, {%8,%9}, {%0,%1,%2,%3};"
        : "+f"(c[0]), "+f"(c[1]), "+f"(c[2]), "+f"(c[3])
        : "r"(a0), "r"(a1), "r"(a2), "r"(a3), "r"(b0), "r"(b1));
}

// ---------------- prep: fp16 convert + 32-wide K-permute + exact row norms ----------------
__global__ void prep_kernel(const float* __restrict__ x1, const float* __restrict__ x2) {
    __shared__ float buf[8][256];
    int wib   = threadIdx.x >> 5;
    int gw    = (blockIdx.x * blockDim.x + threadIdx.x) >> 5;  // global warp [0,16384)
    int lane  = threadIdx.x & 31;
    int which = gw >> 13;                 // 0 -> x1, 1 -> x2
    int row   = gw & (NROWS - 1);
    const float4* src = reinterpret_cast<const float4*>((which ? x2 : x1) + (size_t)row * DDIM);

    float s = 0.f;
#pragma unroll
    for (int i = 0; i < 2; i++) {
        int q = lane + 32 * i;            // 64 float4 per row
        float4 v = src[q];
        s += v.x * v.x + v.y * v.y + v.z * v.z + v.w * v.w;   // exact fp32 norm
        *reinterpret_cast<float4*>(&buf[wib][q * 4]) = v;
    }
    __syncwarp();
#pragma unroll
    for (int off = 16; off; off >>= 1) s += __shfl_xor_sync(0xffffffff, s, off);
    if (lane == 0) g_sq[which][row] = s;

    // permuted fp16 writeback, one uint32 (2 halves) per thread-iter:
    // dst pair (j0, j0+1) <- cols (grp + 2q + 8m, +1), q=(j0&31)>>3, m=((j0&7)>>1)
    uint32_t* dst32 = reinterpret_cast<uint32_t*>(&g_h[which][(size_t)row * DDIM]);
#pragma unroll
    for (int i = 0; i < 4; i++) {
        int pidx = i * 32 + lane;         // pair index 0..127
        int j0   = pidx * 2;
        int grp  = j0 & ~31;
        int p    = j0 & 31;
        int q    = p >> 3;
        int m    = (p & 7) >> 1;
        int col  = grp + 2 * q + 8 * m;
        __half h0 = __float2half_rn(buf[wib][col]);
        __half h1 = __float2half_rn(buf[wib][col + 1]);
        dst32[pidx] = (uint32_t)__half_as_ushort(h0)
                    | ((uint32_t)__half_as_ushort(h1) << 16);
    }
}

// ---------------- main GEMM + epilogue ----------------
#define BM 128
#define BN 64
#define BK 32
#define NK (DDIM / BK)            // 8 K-iterations
#define STAGES 4
#define ROWB 64                   // 32 fp16 per smem row; naturally conflict-free
#define A_BYTES (BM * ROWB)       // 8192
#define B_BYTES (BN * ROWB)       // 4096
#define STAGE_BYTES (A_BYTES + B_BYTES)     // 12288
#define SMEM_TOTAL (STAGES * STAGE_BYTES)   // 49152 -> 2 CTAs/SM easily

// 8 warps; each warp owns a 32x32 output tile (32 accumulators/thread).
__global__ void __launch_bounds__(256, 2)
cdist_kernel(float* __restrict__ out) {
    extern __shared__ char smem_raw[];
    const uint32_t sbase = smem_u32(smem_raw);

    const int tid = threadIdx.x;
    const int wid = tid >> 5;
    const int lid = tid & 31;
    const int m0 = blockIdx.y * BM;
    const int n0 = blockIdx.x * BN;
    const int g   = lid >> 2;         // 0..7
    const int tig = lid & 3;          // 0..3
    const int wm = (wid & 3) * 32;    // warp m-offset (4 warps in M)
    const int wn = (wid >> 2) * 32;   // warp n-offset (2 warps in N)

    // ---- loop-invariant cp.async addressing ----
    // A: 512 granules (128 rows x 4); thread t covers rows t/4 and t/4+64.
    // B: 256 granules (64 rows x 4);  thread t covers row t/4.
    const int crow = tid >> 2;        // 0..63
    const int gq   = tid & 3;         // 16B granule within 32-col chunk
    const char* gA = (const char*)g_h[0]
                   + ((size_t)(m0 + crow) * DDIM + (size_t)gq * 8) * 2;
    const char* gB = (const char*)g_h[1]
                   + ((size_t)(n0 + crow) * DDIM + (size_t)gq * 8) * 2;
    const uint32_t sdA = sbase + (uint32_t)crow * ROWB + (uint32_t)gq * 16u;
    const uint32_t sdB = sbase + A_BYTES + (uint32_t)crow * ROWB + (uint32_t)gq * 16u;

    auto load_stage = [&](int kc, int s) {   // kc, s compile-time under unroll
        cp16(sdA + s * STAGE_BYTES,                 gA + kc * 64);
        cp16(sdA + s * STAGE_BYTES + 64 * ROWB,     gA + kc * 64 + (size_t)64 * DDIM * 2);
        cp16(sdB + s * STAGE_BYTES,                 gB + kc * 64);
        cp_commit();
    };

    // ---- loop-invariant fragment bases (mt/nt offsets are immediates) ----
    const uint32_t abase = sbase + (uint32_t)(wm + g) * ROWB + (uint32_t)tig * 16u;
    const uint32_t bbase = sbase + A_BYTES + (uint32_t)(wn + g) * ROWB + (uint32_t)tig * 16u;

    // prologue: STAGES-1 stages in flight
    load_stage(0, 0);
    load_stage(1, 1);
    load_stage(2, 2);

    float c[2][4][4];
#pragma unroll
    for (int mt = 0; mt < 2; mt++)
#pragma unroll
        for (int nt = 0; nt < 4; nt++)
#pragma unroll
            for (int i = 0; i < 4; i++) c[mt][nt][i] = 0.f;

#pragma unroll
    for (int kc = 0; kc < NK; kc++) {
        cp_wait<STAGES - 2>();     // stage kc landed
        __syncthreads();           // all warps done reading buf being refilled

        if (kc + STAGES - 1 < NK) load_stage(kc + STAGES - 1, (kc + STAGES - 1) % STAGES);
        else cp_commit();          // empty group keeps wait_group arithmetic uniform

        const uint32_t soff = (uint32_t)((kc % STAGES) * STAGE_BYTES);
        const uint32_t ab = abase + soff;
        const uint32_t bb = bbase + soff;

        // fragment loads: one LDS.128 per row covers BOTH k16-steps
        uint4 alo[2], ahi[2], bv[4];
#pragma unroll
        for (int nt = 0; nt < 4; nt++)
            bv[nt] = lds128(bb + nt * (8 * ROWB));             // rows wn+nt*8+g
#pragma unroll
        for (int mt = 0; mt < 2; mt++) {
            alo[mt] = lds128(ab + mt * (16 * ROWB));           // row wm+mt*16+g
            ahi[mt] = lds128(ab + mt * (16 * ROWB) + 8 * ROWB);// row +8
        }

        // k16-step 0: frags .x/.y
#pragma unroll
        for (int mt = 0; mt < 2; mt++)
#pragma unroll
            for (int nt = 0; nt < 4; nt++)
                mma_f16(c[mt][nt], alo[mt].x, ahi[mt].x, alo[mt].y, ahi[mt].y,
                        bv[nt].x, bv[nt].y);
        // k16-step 1: frags .z/.w
#pragma unroll
        for (int mt = 0; mt < 2; mt++)
#pragma unroll
            for (int nt = 0; nt < 4; nt++)
                mma_f16(c[mt][nt], alo[mt].z, ahi[mt].z, alo[mt].w, ahi[mt].w,
                        bv[nt].z, bv[nt].w);
    }

    // ---- epilogue: d = sqrt(max(sq1 + sq2 - 2*cross, 0)) ----
    const float* sq1 = g_sq[0] + m0;
    const float* sq2 = g_sq[1] + n0;
#pragma unroll
    for (int mt = 0; mt < 2; mt++) {
        int r0 = wm + mt * 16 + g;
        float s1a = sq1[r0];
        float s1b = sq1[r0 + 8];
        float* o0 = out + (size_t)(m0 + r0) * NROWS + n0;
        float* o1 = o0 + (size_t)8 * NROWS;
#pragma unroll
        for (int nt = 0; nt < 4; nt++) {
            int cc = wn + nt * 8 + 2 * tig;
            float s2a = sq2[cc];
            float s2b = sq2[cc + 1];
            float2 v0, v1;
            v0.x = sqrtf(fmaxf(fmaf(-2.f, c[mt][nt][0], s1a + s2a), 0.f));
            v0.y = sqrtf(fmaxf(fmaf(-2.f, c[mt][nt][1], s1a + s2b), 0.f));
            v1.x = sqrtf(fmaxf(fmaf(-2.f, c[mt][nt][2], s1b + s2a), 0.f));
            v1.y = sqrtf(fmaxf(fmaf(-2.f, c[mt][nt][3], s1b + s2b), 0.f));
            *reinterpret_cast<float2*>(o0 + cc) = v0;
            *reinterpret_cast<float2*>(o1 + cc) = v1;
        }
    }
}

// ---------------- launch ----------------
extern "C" void kernel_launch(void* const* d_in, const int* in_sizes, int n_in,
                              void* d_out, int out_size) {
    (void)in_sizes; (void)n_in; (void)out_size;
    const float* x1 = (const float*)d_in[0];
    const float* x2 = (const float*)d_in[1];
    float* out = (float*)d_out;

    prep_kernel<<<2048, 256>>>(x1, x2);

    static bool attr_set = false;
    if (!attr_set) {
        cudaFuncSetAttribute(cdist_kernel,
                             cudaFuncAttributeMaxDynamicSharedMemorySize, SMEM_TOTAL);
        attr_set = true;
    }
    dim3 grid(NROWS / BN, NROWS / BM);   // (128, 64)
    cdist_kernel<<<grid, 256, SMEM_TOTAL>>>(out);
}

// round 15
// speedup vs baseline: 1.3954x; 1.0743x over previous
#include <cuda_runtime.h>
#include <cuda_fp16.h>
#include <cstdint>

#define NROWS 8192
#define DDIM  256

// ---------------- device scratch (allocation-free) ----------------
// fp16 copies; within each 32-column K-group, 16B granule q (8 fp16) holds
// orig cols {2q,2q+1, 2q+8,2q+9, 2q+16,2q+17, 2q+24,2q+25} — thread tig=q's
// m16n8k16 fragments for BOTH k16-steps. One LDS.128 per row per 32-col chunk.
__device__ __half g_h[2][NROWS * DDIM];
__device__ float  g_sq[2][NROWS];        // exact fp32 row norms

// ---------------- helpers ----------------
__device__ __forceinline__ uint32_t smem_u32(const void* p) {
    uint32_t a;
    asm("{ .reg .u64 t; cvta.to.shared.u64 t, %1; cvt.u32.u64 %0, t; }" : "=r"(a) : "l"(p));
    return a;
}
__device__ __forceinline__ uint4 lds128(uint32_t a) {
    uint4 v;
    asm volatile("ld.shared.v4.b32 {%0,%1,%2,%3}, [%4];"
                 : "=r"(v.x), "=r"(v.y), "=r"(v.z), "=r"(v.w) : "r"(a));
    return v;
}
__device__ __forceinline__ void cp16(uint32_t dst, const void* src) {
    asm volatile("cp.async.cg.shared.global [%0], [%1], 16;" :: "r"(dst), "l"(src));
}
__device__ __forceinline__ void cp_commit() {
    asm volatile("cp.async.commit_group;" ::: "memory");
}
template <int N> __device__ __forceinline__ void cp_wait() {
    asm volatile("cp.async.wait_group %0;" :: "n"(N) : "memory");
}
__device__ __forceinline__ void mma_f16(float* c, uint32_t a0, uint32_t a1,
                                        uint32_t a2, uint32_t a3,
                                        uint32_t b0, uint32_t b1) {
    asm volatile(
        "mma.sync.aligned.m16n8k16.row.col.f32.f16.f16.f32 "
        "{%0,%1,%2,%3}, {%4,%5,%6,%7}, {%8,%9}, {%0,%1,%2,%3};"
        : "+f"(c[0]), "+f"(c[1]), "+f"(c[2]), "+f"(c[3])
        : "r"(a0), "r"(a1), "r"(a2), "r"(a3), "r"(b0), "r"(b1));
}

// ---------------- prep: fp16 convert + 32-wide K-permute + exact row norms ----------------
__global__ void prep_kernel(const float* __restrict__ x1, const float* __restrict__ x2) {
    __shared__ float buf[8][256];
    int wib   = threadIdx.x >> 5;
    int gw    = (blockIdx.x * blockDim.x + threadIdx.x) >> 5;  // global warp [0,16384)
    int lane  = threadIdx.x & 31;
    int which = gw >> 13;                 // 0 -> x1, 1 -> x2
    int row   = gw & (NROWS - 1);
    const float4* src = reinterpret_cast<const float4*>((which ? x2 : x1) + (size_t)row * DDIM);

    float s = 0.f;
#pragma unroll
    for (int i = 0; i < 2; i++) {
        int q = lane + 32 * i;            // 64 float4 per row
        float4 v = src[q];
        s += v.x * v.x + v.y * v.y + v.z * v.z + v.w * v.w;   // exact fp32 norm
        *reinterpret_cast<float4*>(&buf[wib][q * 4]) = v;
    }
    __syncwarp();
#pragma unroll
    for (int off = 16; off; off >>= 1) s += __shfl_xor_sync(0xffffffff, s, off);
    if (lane == 0) g_sq[which][row] = s;

    // permuted fp16 writeback, one uint32 (2 halves) per thread-iter:
    // dst pair (j0, j0+1) <- cols (grp + 2q + 8m, +1), q=(j0&31)>>3, m=((j0&7)>>1)
    uint32_t* dst32 = reinterpret_cast<uint32_t*>(&g_h[which][(size_t)row * DDIM]);
#pragma unroll
    for (int i = 0; i < 4; i++) {
        int pidx = i * 32 + lane;         // pair index 0..127
        int j0   = pidx * 2;
        int grp  = j0 & ~31;
        int p    = j0 & 31;
        int q    = p >> 3;
        int m    = (p & 7) >> 1;
        int col  = grp + 2 * q + 8 * m;
        __half h0 = __float2half_rn(buf[wib][col]);
        __half h1 = __float2half_rn(buf[wib][col + 1]);
        dst32[pidx] = (uint32_t)__half_as_ushort(h0)
                    | ((uint32_t)__half_as_ushort(h1) << 16);
    }
}

// ---------------- main GEMM + epilogue ----------------
#define BM 64
#define BN 64
#define BK 32
#define NK (DDIM / BK)            // 8 K-iterations
#define STAGES 4
#define ROWB 64                   // 32 fp16 per smem row; naturally conflict-free
#define A_BYTES (BM * ROWB)       // 4096
#define B_BYTES (BN * ROWB)       // 4096
#define STAGE_BYTES (A_BYTES + B_BYTES)     // 8192
#define SMEM_TOTAL (STAGES * STAGE_BYTES)   // 32768 -> 5 CTAs/SM (reg-limited)

// 4 warps; each warp owns a 32x32 output tile (32 accumulators/thread).
__global__ void __launch_bounds__(128, 5)
cdist_kernel(float* __restrict__ out) {
    extern __shared__ char smem_raw[];
    const uint32_t sbase = smem_u32(smem_raw);

    const int tid = threadIdx.x;
    const int wid = tid >> 5;
    const int lid = tid & 31;
    const int m0 = blockIdx.y * BM;
    const int n0 = blockIdx.x * BN;
    const int g   = lid >> 2;         // 0..7
    const int tig = lid & 3;          // 0..3
    const int wm = (wid & 1) * 32;    // warp m-offset (2 warps in M)
    const int wn = (wid >> 1) * 32;   // warp n-offset (2 warps in N)

    // ---- loop-invariant cp.async addressing ----
    // A: 256 granules (64 rows x 4); thread t covers rows t/4 and t/4+32.
    // B: likewise.
    const int crow = tid >> 2;        // 0..31
    const int gq   = tid & 3;         // 16B granule within 32-col chunk
    const char* gA = (const char*)g_h[0]
                   + ((size_t)(m0 + crow) * DDIM + (size_t)gq * 8) * 2;
    const char* gB = (const char*)g_h[1]
                   + ((size_t)(n0 + crow) * DDIM + (size_t)gq * 8) * 2;
    const uint32_t sdA = sbase + (uint32_t)crow * ROWB + (uint32_t)gq * 16u;
    const uint32_t sdB = sbase + A_BYTES + (uint32_t)crow * ROWB + (uint32_t)gq * 16u;

    auto load_stage = [&](int kc, int s) {   // kc, s compile-time under unroll
        cp16(sdA + s * STAGE_BYTES,             gA + kc * 64);
        cp16(sdA + s * STAGE_BYTES + 32 * ROWB, gA + kc * 64 + (size_t)32 * DDIM * 2);
        cp16(sdB + s * STAGE_BYTES,             gB + kc * 64);
        cp16(sdB + s * STAGE_BYTES + 32 * ROWB, gB + kc * 64 + (size_t)32 * DDIM * 2);
        cp_commit();
    };

    // ---- loop-invariant fragment bases (mt/nt offsets are immediates) ----
    const uint32_t abase = sbase + (uint32_t)(wm + g) * ROWB + (uint32_t)tig * 16u;
    const uint32_t bbase = sbase + A_BYTES + (uint32_t)(wn + g) * ROWB + (uint32_t)tig * 16u;

    // prologue: STAGES-1 stages in flight
    load_stage(0, 0);
    load_stage(1, 1);
    load_stage(2, 2);

    float c[2][4][4];
#pragma unroll
    for (int mt = 0; mt < 2; mt++)
#pragma unroll
        for (int nt = 0; nt < 4; nt++)
#pragma unroll
            for (int i = 0; i < 4; i++) c[mt][nt][i] = 0.f;

#pragma unroll
    for (int kc = 0; kc < NK; kc++) {
        cp_wait<STAGES - 2>();     // stage kc landed
        __syncthreads();           // all warps done reading buf being refilled

        if (kc + STAGES - 1 < NK) load_stage(kc + STAGES - 1, (kc + STAGES - 1) % STAGES);
        else cp_commit();          // empty group keeps wait_group arithmetic uniform

        const uint32_t soff = (uint32_t)((kc % STAGES) * STAGE_BYTES);
        const uint32_t ab = abase + soff;
        const uint32_t bb = bbase + soff;

        // fragment loads: one LDS.128 per row covers BOTH k16-steps
        uint4 alo[2], ahi[2], bv[4];
#pragma unroll
        for (int nt = 0; nt < 4; nt++)
            bv[nt] = lds128(bb + nt * (8 * ROWB));             // rows wn+nt*8+g
#pragma unroll
        for (int mt = 0; mt < 2; mt++) {
            alo[mt] = lds128(ab + mt * (16 * ROWB));           // row wm+mt*16+g
            ahi[mt] = lds128(ab + mt * (16 * ROWB) + 8 * ROWB);// row +8
        }

        // k16-step 0: frags .x/.y
#pragma unroll
        for (int mt = 0; mt < 2; mt++)
#pragma unroll
            for (int nt = 0; nt < 4; nt++)
                mma_f16(c[mt][nt], alo[mt].x, ahi[mt].x, alo[mt].y, ahi[mt].y,
                        bv[nt].x, bv[nt].y);
        // k16-step 1: frags .z/.w
#pragma unroll
        for (int mt = 0; mt < 2; mt++)
#pragma unroll
            for (int nt = 0; nt < 4; nt++)
                mma_f16(c[mt][nt], alo[mt].z, ahi[mt].z, alo[mt].w, ahi[mt].w,
                        bv[nt].z, bv[nt].w);
    }

    // ---- epilogue: d = sqrt(max(sq1 + sq2 - 2*cross, 0)) ----
    const float* sq1 = g_sq[0] + m0;
    const float* sq2 = g_sq[1] + n0;
#pragma unroll
    for (int mt = 0; mt < 2; mt++) {
        int r0 = wm + mt * 16 + g;
        float s1a = sq1[r0];
        float s1b = sq1[r0 + 8];
        float* o0 = out + (size_t)(m0 + r0) * NROWS + n0;
        float* o1 = o0 + (size_t)8 * NROWS;
#pragma unroll
        for (int nt = 0; nt < 4; nt++) {
            int cc = wn + nt * 8 + 2 * tig;
            float s2a = sq2[cc];
            float s2b = sq2[cc + 1];
            float2 v0, v1;
            v0.x = sqrtf(fmaxf(fmaf(-2.f, c[mt][nt][0], s1a + s2a), 0.f));
            v0.y = sqrtf(fmaxf(fmaf(-2.f, c[mt][nt][1], s1a + s2b), 0.f));
            v1.x = sqrtf(fmaxf(fmaf(-2.f, c[mt][nt][2], s1b + s2a), 0.f));
            v1.y = sqrtf(fmaxf(fmaf(-2.f, c[mt][nt][3], s1b + s2b), 0.f));
            *reinterpret_cast<float2*>(o0 + cc) = v0;
            *reinterpret_cast<float2*>(o1 + cc) = v1;
        }
    }
}

// ---------------- launch ----------------
extern "C" void kernel_launch(void* const* d_in, const int* in_sizes, int n_in,
                              void* d_out, int out_size) {
    (void)in_sizes; (void)n_in; (void)out_size;
    const float* x1 = (const float*)d_in[0];
    const float* x2 = (const float*)d_in[1];
    float* out = (float*)d_out;

    prep_kernel<<<2048, 256>>>(x1, x2);

    static bool attr_set = false;
    if (!attr_set) {
        cudaFuncSetAttribute(cdist_kernel,
                             cudaFuncAttributeMaxDynamicSharedMemorySize, SMEM_TOTAL);
        attr_set = true;
    }
    dim3 grid(NROWS / BN, NROWS / BM);   // (128, 128)
    cdist_kernel<<<grid, 128, SMEM_TOTAL>>>(out);
}

// round 16
// speedup vs baseline: 1.4010x; 1.0039x over previous
#include <cuda_runtime.h>
#include <cuda_fp16.h>
#include <cstdint>

#define NROWS 8192
#define DDIM  256

// ---------------- device scratch (allocation-free) ----------------
// fp16 copies; within each 32-column K-group, 16B granule q (8 fp16) holds
// orig cols {2q,2q+1, 2q+8,2q+9, 2q+16,2q+17, 2q+24,2q+25} — thread tig=q's
// m16n8k16 fragments for BOTH k16-steps. One LDS.128 per row per 32-col chunk.
__device__ __half g_h[2][NROWS * DDIM];
__device__ float  g_sq[2][NROWS];        // exact fp32 row norms

// ---------------- helpers ----------------
__device__ __forceinline__ uint32_t smem_u32(const void* p) {
    uint32_t a;
    asm("{ .reg .u64 t; cvta.to.shared.u64 t, %1; cvt.u32.u64 %0, t; }" : "=r"(a) : "l"(p));
    return a;
}
__device__ __forceinline__ uint4 lds128(uint32_t a) {
    uint4 v;
    asm volatile("ld.shared.v4.b32 {%0,%1,%2,%3}, [%4];"
                 : "=r"(v.x), "=r"(v.y), "=r"(v.z), "=r"(v.w) : "r"(a));
    return v;
}
__device__ __forceinline__ void cp16(uint32_t dst, const void* src) {
    asm volatile("cp.async.cg.shared.global [%0], [%1], 16;" :: "r"(dst), "l"(src));
}
__device__ __forceinline__ void cp_commit() {
    asm volatile("cp.async.commit_group;" ::: "memory");
}
template <int N> __device__ __forceinline__ void cp_wait() {
    asm volatile("cp.async.wait_group %0;" :: "n"(N) : "memory");
}
__device__ __forceinline__ void mma_f16(float* c, uint32_t a0, uint32_t a1,
                                        uint32_t a2, uint32_t a3,
                                        uint32_t b0, uint32_t b1) {
    asm volatile(
        "mma.sync.aligned.m16n8k16.row.col.f32.f16.f16.f32 "
        "{%0,%1,%2,%3}, {%4,%5,%6,%7}, {%8,%9}, {%0,%1,%2,%3};"
        : "+f"(c[0]), "+f"(c[1]), "+f"(c[2]), "+f"(c[3])
        : "r"(a0), "r"(a1), "r"(a2), "r"(a3), "r"(b0), "r"(b1));
}

// ---------------- prep: fp16 convert + 32-wide K-permute + exact row norms ----------------
__global__ void prep_kernel(const float* __restrict__ x1, const float* __restrict__ x2) {
    __shared__ float buf[8][256];
    int wib   = threadIdx.x >> 5;
    int gw    = (blockIdx.x * blockDim.x + threadIdx.x) >> 5;  // global warp [0,16384)
    int lane  = threadIdx.x & 31;
    int which = gw >> 13;                 // 0 -> x1, 1 -> x2
    int row   = gw & (NROWS - 1);
    const float4* src = reinterpret_cast<const float4*>((which ? x2 : x1) + (size_t)row * DDIM);

    float s = 0.f;
#pragma unroll
    for (int i = 0; i < 2; i++) {
        int q = lane + 32 * i;            // 64 float4 per row
        float4 v = src[q];
        s += v.x * v.x + v.y * v.y + v.z * v.z + v.w * v.w;   // exact fp32 norm
        *reinterpret_cast<float4*>(&buf[wib][q * 4]) = v;
    }
    __syncwarp();
#pragma unroll
    for (int off = 16; off; off >>= 1) s += __shfl_xor_sync(0xffffffff, s, off);
    if (lane == 0) g_sq[which][row] = s;

    // permuted fp16 writeback, one uint32 (2 halves) per thread-iter:
    // dst pair (j0, j0+1) <- cols (grp + 2q + 8m, +1), q=(j0&31)>>3, m=((j0&7)>>1)
    uint32_t* dst32 = reinterpret_cast<uint32_t*>(&g_h[which][(size_t)row * DDIM]);
#pragma unroll
    for (int i = 0; i < 4; i++) {
        int pidx = i * 32 + lane;         // pair index 0..127
        int j0   = pidx * 2;
        int grp  = j0 & ~31;
        int p    = j0 & 31;
        int q    = p >> 3;
        int m    = (p & 7) >> 1;
        int col  = grp + 2 * q + 8 * m;
        __half h0 = __float2half_rn(buf[wib][col]);
        __half h1 = __float2half_rn(buf[wib][col + 1]);
        dst32[pidx] = (uint32_t)__half_as_ushort(h0)
                    | ((uint32_t)__half_as_ushort(h1) << 16);
    }
}

// ---------------- main GEMM + epilogue ----------------
#define BM 64
#define BN 128
#define BK 32
#define NK (DDIM / BK)            // 8 K-iterations
#define STAGES 4
#define ROWB 64                   // 32 fp16 per smem row; naturally conflict-free
#define A_BYTES (BM * ROWB)       // 4096
#define B_BYTES (BN * ROWB)       // 8192
#define STAGE_BYTES (A_BYTES + B_BYTES)     // 12288
#define SMEM_TOTAL (STAGES * STAGE_BYTES)   // 49152 -> 4 CTAs/SM (reg-limited)

// 4 warps; each warp owns a 32x64 output tile (64 accumulators/thread),
// B fragments processed in halves of 4 to cap register liveness.
__global__ void __launch_bounds__(128, 4)
cdist_kernel(float* __restrict__ out) {
    extern __shared__ char smem_raw[];
    const uint32_t sbase = smem_u32(smem_raw);

    const int tid = threadIdx.x;
    const int wid = tid >> 5;
    const int lid = tid & 31;
    const int m0 = blockIdx.y * BM;
    const int n0 = blockIdx.x * BN;
    const int g   = lid >> 2;         // 0..7
    const int tig = lid & 3;          // 0..3
    const int wm = (wid & 1) * 32;    // warp m-offset (2 warps in M)
    const int wn = (wid >> 1) * 64;   // warp n-offset (2 warps in N)

    // ---- loop-invariant cp.async addressing ----
    // A: 256 granules (64 rows x 4); thread covers rows crow, crow+32.
    // B: 512 granules (128 rows x 4); thread covers crow, +32, +64, +96.
    const int crow = tid >> 2;        // 0..31
    const int gq   = tid & 3;         // 16B granule within 32-col chunk
    const char* gA = (const char*)g_h[0]
                   + ((size_t)(m0 + crow) * DDIM + (size_t)gq * 8) * 2;
    const char* gB = (const char*)g_h[1]
                   + ((size_t)(n0 + crow) * DDIM + (size_t)gq * 8) * 2;
    const uint32_t sdA = sbase + (uint32_t)crow * ROWB + (uint32_t)gq * 16u;
    const uint32_t sdB = sbase + A_BYTES + (uint32_t)crow * ROWB + (uint32_t)gq * 16u;

    auto load_stage = [&](int kc, int s) {   // kc, s compile-time under unroll
        cp16(sdA + s * STAGE_BYTES,             gA + kc * 64);
        cp16(sdA + s * STAGE_BYTES + 32 * ROWB, gA + kc * 64 + (size_t)32 * DDIM * 2);
#pragma unroll
        for (int i = 0; i < 4; i++)
            cp16(sdB + s * STAGE_BYTES + i * (32 * ROWB),
                 gB + kc * 64 + (size_t)i * 32 * DDIM * 2);
        cp_commit();
    };

    // ---- loop-invariant fragment bases (nt offsets are immediates) ----
    const uint32_t abase = sbase + (uint32_t)(wm + g) * ROWB + (uint32_t)tig * 16u;
    const uint32_t bbase = sbase + A_BYTES + (uint32_t)(wn + g) * ROWB + (uint32_t)tig * 16u;

    // prologue: STAGES-1 stages in flight
    load_stage(0, 0);
    load_stage(1, 1);
    load_stage(2, 2);

    float c[2][8][4];
#pragma unroll
    for (int mt = 0; mt < 2; mt++)
#pragma unroll
        for (int nt = 0; nt < 8; nt++)
#pragma unroll
            for (int i = 0; i < 4; i++) c[mt][nt][i] = 0.f;

#pragma unroll
    for (int kc = 0; kc < NK; kc++) {
        cp_wait<STAGES - 2>();     // stage kc landed
        __syncthreads();           // all warps done reading buf being refilled

        if (kc + STAGES - 1 < NK) load_stage(kc + STAGES - 1, (kc + STAGES - 1) % STAGES);
        else cp_commit();          // empty group keeps wait_group arithmetic uniform

        const uint32_t soff = (uint32_t)((kc % STAGES) * STAGE_BYTES);
        const uint32_t ab = abase + soff;
        const uint32_t bb = bbase + soff;

        // A fragments for the whole kc (both k16-steps): 4 LDS.128
        uint4 alo[2], ahi[2];
#pragma unroll
        for (int mt = 0; mt < 2; mt++) {
            alo[mt] = lds128(ab + mt * (16 * ROWB));            // row wm+mt*16+g
            ahi[mt] = lds128(ab + mt * (16 * ROWB) + 8 * ROWB); // row +8
        }

        // B fragments in two halves of 4 (caps live registers)
#pragma unroll
        for (int h = 0; h < 2; h++) {
            uint4 bv[4];
#pragma unroll
            for (int j = 0; j < 4; j++)
                bv[j] = lds128(bb + (h * 4 + j) * (8 * ROWB));  // rows wn+nt*8+g

            // k16-step 0: frags .x/.y
#pragma unroll
            for (int mt = 0; mt < 2; mt++)
#pragma unroll
                for (int j = 0; j < 4; j++)
                    mma_f16(c[mt][h * 4 + j], alo[mt].x, ahi[mt].x, alo[mt].y, ahi[mt].y,
                            bv[j].x, bv[j].y);
            // k16-step 1: frags .z/.w
#pragma unroll
            for (int mt = 0; mt < 2; mt++)
#pragma unroll
                for (int j = 0; j < 4; j++)
                    mma_f16(c[mt][h * 4 + j], alo[mt].z, ahi[mt].z, alo[mt].w, ahi[mt].w,
                            bv[j].z, bv[j].w);
        }
    }

    // ---- epilogue: d = sqrt(max(sq1 + sq2 - 2*cross, 0)) ----
    const float* sq1 = g_sq[0] + m0;
    const float* sq2 = g_sq[1] + n0;
#pragma unroll
    for (int mt = 0; mt < 2; mt++) {
        int r0 = wm + mt * 16 + g;
        float s1a = sq1[r0];
        float s1b = sq1[r0 + 8];
        float* o0 = out + (size_t)(m0 + r0) * NROWS + n0;
        float* o1 = o0 + (size_t)8 * NROWS;
#pragma unroll
        for (int nt = 0; nt < 8; nt++) {
            int cc = wn + nt * 8 + 2 * tig;
            float s2a = sq2[cc];
            float s2b = sq2[cc + 1];
            float2 v0, v1;
            v0.x = sqrtf(fmaxf(fmaf(-2.f, c[mt][nt][0], s1a + s2a), 0.f));
            v0.y = sqrtf(fmaxf(fmaf(-2.f, c[mt][nt][1], s1a + s2b), 0.f));
            v1.x = sqrtf(fmaxf(fmaf(-2.f, c[mt][nt][2], s1b + s2a), 0.f));
            v1.y = sqrtf(fmaxf(fmaf(-2.f, c[mt][nt][3], s1b + s2b), 0.f));
            *reinterpret_cast<float2*>(o0 + cc) = v0;
            *reinterpret_cast<float2*>(o1 + cc) = v1;
        }
    }
}

// ---------------- launch ----------------
extern "C" void kernel_launch(void* const* d_in, const int* in_sizes, int n_in,
                              void* d_out, int out_size) {
    (void)in_sizes; (void)n_in; (void)out_size;
    const float* x1 = (const float*)d_in[0];
    const float* x2 = (const float*)d_in[1];
    float* out = (float*)d_out;

    prep_kernel<<<2048, 256>>>(x1, x2);

    static bool attr_set = false;
    if (!attr_set) {
        cudaFuncSetAttribute(cdist_kernel,
                             cudaFuncAttributeMaxDynamicSharedMemorySize, SMEM_TOTAL);
        attr_set = true;
    }
    dim3 grid(NROWS / BN, NROWS / BM);   // (64, 128)
    cdist_kernel<<<grid, 128, SMEM_TOTAL>>>(out);
}

// round 17
// speedup vs baseline: 1.4591x; 1.0415x over previous
#include <cuda_runtime.h>
#include <cuda_fp16.h>
#include <cstdint>

#define NROWS 8192
#define DDIM  256

// ---------------- device scratch (allocation-free) ----------------
// fp16 copies; within each 32-column K-group, 16B granule q (8 fp16) holds
// orig cols {2q,2q+1, 2q+8,2q+9, 2q+16,2q+17, 2q+24,2q+25} — thread tig=q's
// m16n8k16 fragments for BOTH k16-steps. One LDS.128 per row per 32-col chunk.
__device__ __half g_h[2][NROWS * DDIM];
__device__ float  g_sq[2][NROWS];        // exact fp32 row norms

// ---------------- helpers ----------------
__device__ __forceinline__ uint32_t smem_u32(const void* p) {
    uint32_t a;
    asm("{ .reg .u64 t; cvta.to.shared.u64 t, %1; cvt.u32.u64 %0, t; }" : "=r"(a) : "l"(p));
    return a;
}
__device__ __forceinline__ uint4 lds128(uint32_t a) {
    uint4 v;
    asm volatile("ld.shared.v4.b32 {%0,%1,%2,%3}, [%4];"
                 : "=r"(v.x), "=r"(v.y), "=r"(v.z), "=r"(v.w) : "r"(a));
    return v;
}
__device__ __forceinline__ void cp16(uint32_t dst, const void* src) {
    asm volatile("cp.async.cg.shared.global [%0], [%1], 16;" :: "r"(dst), "l"(src));
}
__device__ __forceinline__ void cp_commit() {
    asm volatile("cp.async.commit_group;" ::: "memory");
}
template <int N> __device__ __forceinline__ void cp_wait() {
    asm volatile("cp.async.wait_group %0;" :: "n"(N) : "memory");
}
__device__ __forceinline__ void mma_f16(float* c, uint32_t a0, uint32_t a1,
                                        uint32_t a2, uint32_t a3,
                                        uint32_t b0, uint32_t b1) {
    asm volatile(
        "mma.sync.aligned.m16n8k16.row.col.f32.f16.f16.f32 "
        "{%0,%1,%2,%3}, {%4,%5,%6,%7}, {%8,%9}, {%0,%1,%2,%3};"
        : "+f"(c[0]), "+f"(c[1]), "+f"(c[2]), "+f"(c[3])
        : "r"(a0), "r"(a1), "r"(a2), "r"(a3), "r"(b0), "r"(b1));
}

// ---------------- prep: fp16 convert + 32-wide K-permute + exact row norms ----------------
__global__ void prep_kernel(const float* __restrict__ x1, const float* __restrict__ x2) {
    __shared__ float buf[8][256];
    int wib   = threadIdx.x >> 5;
    int gw    = (blockIdx.x * blockDim.x + threadIdx.x) >> 5;  // global warp [0,16384)
    int lane  = threadIdx.x & 31;
    int which = gw >> 13;                 // 0 -> x1, 1 -> x2
    int row   = gw & (NROWS - 1);
    const float4* src = reinterpret_cast<const float4*>((which ? x2 : x1) + (size_t)row * DDIM);

    float s = 0.f;
#pragma unroll
    for (int i = 0; i < 2; i++) {
        int q = lane + 32 * i;            // 64 float4 per row
        float4 v = src[q];
        s += v.x * v.x + v.y * v.y + v.z * v.z + v.w * v.w;   // exact fp32 norm
        *reinterpret_cast<float4*>(&buf[wib][q * 4]) = v;
    }
    __syncwarp();
#pragma unroll
    for (int off = 16; off; off >>= 1) s += __shfl_xor_sync(0xffffffff, s, off);
    if (lane == 0) g_sq[which][row] = s;

    // permuted fp16 writeback, one uint32 (2 halves) per thread-iter:
    // dst pair (j0, j0+1) <- cols (grp + 2q + 8m, +1), q=(j0&31)>>3, m=((j0&7)>>1)
    uint32_t* dst32 = reinterpret_cast<uint32_t*>(&g_h[which][(size_t)row * DDIM]);
#pragma unroll
    for (int i = 0; i < 4; i++) {
        int pidx = i * 32 + lane;         // pair index 0..127
        int j0   = pidx * 2;
        int grp  = j0 & ~31;
        int p    = j0 & 31;
        int q    = p >> 3;
        int m    = (p & 7) >> 1;
        int col  = grp + 2 * q + 8 * m;
        __half h0 = __float2half_rn(buf[wib][col]);
        __half h1 = __float2half_rn(buf[wib][col + 1]);
        dst32[pidx] = (uint32_t)__half_as_ushort(h0)
                    | ((uint32_t)__half_as_ushort(h1) << 16);
    }
}

// ---------------- main GEMM + epilogue ----------------
#define BM 64
#define BN 64
#define BK 64
#define NK (DDIM / BK)            // 4 K-iterations
#define STAGES 2
#define ROWB 128                  // 64 fp16 per smem row; granule-parity XOR swizzle
#define A_BYTES (BM * ROWB)       // 8192
#define B_BYTES (BN * ROWB)       // 8192
#define STAGE_BYTES (A_BYTES + B_BYTES)     // 16384
#define SMEM_TOTAL (STAGES * STAGE_BYTES)   // 32768 -> 5 CTAs/SM (reg-limited)

// 4 warps; each warp owns a 32x32 output tile (32 accumulators/thread).
__global__ void __launch_bounds__(128, 5)
cdist_kernel(float* __restrict__ out) {
    extern __shared__ char smem_raw[];
    const uint32_t sbase = smem_u32(smem_raw);

    const int tid = threadIdx.x;
    const int wid = tid >> 5;
    const int lid = tid & 31;
    const int m0 = blockIdx.y * BM;
    const int n0 = blockIdx.x * BN;
    const int g   = lid >> 2;         // 0..7
    const int tig = lid & 3;          // 0..3
    const int wm = (wid & 1) * 32;    // warp m-offset (2 warps in M)
    const int wn = (wid >> 1) * 32;   // warp n-offset (2 warps in N)

    // ---- loop-invariant cp.async addressing ----
    // 64 rows x 8 granules per matrix per stage; thread covers rows crow+16i.
    const int crow = tid >> 3;        // 0..15
    const int gq   = tid & 7;         // 16B granule within 64-col chunk
    const char* gA = (const char*)g_h[0]
                   + ((size_t)(m0 + crow) * DDIM + (size_t)gq * 8) * 2;
    const char* gB = (const char*)g_h[1]
                   + ((size_t)(n0 + crow) * DDIM + (size_t)gq * 8) * 2;
    // physical granule = gq ^ ((row&1)<<2): odd rows swap 64B halves
    const uint32_t sdA = sbase + (uint32_t)crow * ROWB
                       + (uint32_t)(gq ^ ((crow & 1) << 2)) * 16u;
    const uint32_t sdB = sdA + A_BYTES;

    auto load_stage = [&](int kc, int s) {   // kc, s compile-time under unroll
#pragma unroll
        for (int i = 0; i < 4; i++) {
            cp16(sdA + s * STAGE_BYTES + i * (16 * ROWB),
                 gA + kc * 128 + (size_t)i * 16 * DDIM * 2);
            cp16(sdB + s * STAGE_BYTES + i * (16 * ROWB),
                 gB + kc * 128 + (size_t)i * 16 * DDIM * 2);
        }
        cp_commit();
    };

    // ---- loop-invariant fragment bases; per-k-chunk addr = base ^ (kk<<6) ----
    const uint32_t abase = sbase + (uint32_t)(wm + g) * ROWB + (uint32_t)tig * 16u
                         + (((uint32_t)g & 1u) << 6);
    const uint32_t bbase = sbase + A_BYTES + (uint32_t)(wn + g) * ROWB
                         + (uint32_t)tig * 16u + (((uint32_t)g & 1u) << 6);

    // prologue: 1 stage in flight
    load_stage(0, 0);

    float c[2][4][4];
#pragma unroll
    for (int mt = 0; mt < 2; mt++)
#pragma unroll
        for (int nt = 0; nt < 4; nt++)
#pragma unroll
            for (int i = 0; i < 4; i++) c[mt][nt][i] = 0.f;

#pragma unroll
    for (int kc = 0; kc < NK; kc++) {
        cp_wait<0>();              // only stage kc outstanding here
        __syncthreads();           // data visible to all; old buf fully read

        if (kc + 1 < NK) load_stage(kc + 1, (kc + 1) & 1);

        const uint32_t soff = (uint32_t)((kc & 1) * STAGE_BYTES);
        const uint32_t ab = abase + soff;
        const uint32_t bb = bbase + soff;

#pragma unroll
        for (int kk = 0; kk < 2; kk++) {     // two 32-col chunks per stage
            const uint32_t kx = (uint32_t)kk << 6;
            uint4 alo[2], ahi[2], bv[4];
#pragma unroll
            for (int nt = 0; nt < 4; nt++)
                bv[nt] = lds128((bb + nt * (8 * ROWB)) ^ kx);
#pragma unroll
            for (int mt = 0; mt < 2; mt++) {
                alo[mt] = lds128((ab + mt * (16 * ROWB)) ^ kx);
                ahi[mt] = lds128((ab + mt * (16 * ROWB) + 8 * ROWB) ^ kx);
            }
            // k16-step 0: frags .x/.y
#pragma unroll
            for (int mt = 0; mt < 2; mt++)
#pragma unroll
                for (int nt = 0; nt < 4; nt++)
                    mma_f16(c[mt][nt], alo[mt].x, ahi[mt].x, alo[mt].y, ahi[mt].y,
                            bv[nt].x, bv[nt].y);
            // k16-step 1: frags .z/.w
#pragma unroll
            for (int mt = 0; mt < 2; mt++)
#pragma unroll
                for (int nt = 0; nt < 4; nt++)
                    mma_f16(c[mt][nt], alo[mt].z, ahi[mt].z, alo[mt].w, ahi[mt].w,
                            bv[nt].z, bv[nt].w);
        }
    }

    // ---- epilogue: d = sqrt(max(sq1 + sq2 - 2*cross, 0)) ----
    const float* sq1 = g_sq[0] + m0;
    const float* sq2 = g_sq[1] + n0;
#pragma unroll
    for (int mt = 0; mt < 2; mt++) {
        int r0 = wm + mt * 16 + g;
        float s1a = sq1[r0];
        float s1b = sq1[r0 + 8];
        float* o0 = out + (size_t)(m0 + r0) * NROWS + n0;
        float* o1 = o0 + (size_t)8 * NROWS;
#pragma unroll
        for (int nt = 0; nt < 4; nt++) {
            int cc = wn + nt * 8 + 2 * tig;
            float s2a = sq2[cc];
            float s2b = sq2[cc + 1];
            float2 v0, v1;
            v0.x = sqrtf(fmaxf(fmaf(-2.f, c[mt][nt][0], s1a + s2a), 0.f));
            v0.y = sqrtf(fmaxf(fmaf(-2.f, c[mt][nt][1], s1a + s2b), 0.f));
            v1.x = sqrtf(fmaxf(fmaf(-2.f, c[mt][nt][2], s1b + s2a), 0.f));
            v1.y = sqrtf(fmaxf(fmaf(-2.f, c[mt][nt][3], s1b + s2b), 0.f));
            *reinterpret_cast<float2*>(o0 + cc) = v0;
            *reinterpret_cast<float2*>(o1 + cc) = v1;
        }
    }
}

// ---------------- launch ----------------
extern "C" void kernel_launch(void* const* d_in, const int* in_sizes, int n_in,
                              void* d_out, int out_size) {
    (void)in_sizes; (void)n_in; (void)out_size;
    const float* x1 = (const float*)d_in[0];
    const float* x2 = (const float*)d_in[1];
    float* out = (float*)d_out;

    prep_kernel<<<2048, 256>>>(x1, x2);

    static bool attr_set = false;
    if (!attr_set) {
        cudaFuncSetAttribute(cdist_kernel,
                             cudaFuncAttributeMaxDynamicSharedMemorySize, SMEM_TOTAL);
        attr_set = true;
    }
    dim3 grid(NROWS / BN, NROWS / BM);   // (128, 128)
    cdist_kernel<<<grid, 128, SMEM_TOTAL>>>(out);
}